// round 15
// baseline (speedup 1.0000x reference)
#include <cuda_runtime.h>
#include <cstdint>

// YOLO detection postprocess:
//   in : (16, 25200, 85) f32   [xc, yc, w, h, conf, cls0..cls79]
//   out: (16, 25200, 6)  f32   [xmin, ymin, xmax, ymax, conf*maxcls, argmax] or zeros
//
// Persistent blocks, cp.async.cg 4-stage ring, depth-3 prefetch, HALF footprint:
//   - 16 rows/stage (5440 B) x 4 stages = 21760 B static smem -> 10 blocks/SM
//     (double the independent DRAM streams per SM vs the 43.5 KB variants)
//   - 128 threads: 8 lanes/row, 10 classes each; two interleaved chains +
//     3-level shfl_xor merge with first-index tie-break.

#define CONF_THRESH 0.25f
#define ROW_LEN 85
#define OUT_LEN 6
#define WROWS 16                                     // rows per stage/tile
#define STAGES 4
#define THREADS 128
#define TILE_FLOATS (WROWS * ROW_LEN)                // 1360
#define TILE_VEC4   (TILE_FLOATS / 4)                // 340
#define VEC_FULL    (TILE_VEC4 / THREADS)            // 2
#define VEC_REM     (TILE_VEC4 - VEC_FULL * THREADS) // 84

__device__ __forceinline__ void cp16(uint32_t dst_smem, const void* src_gmem) {
    asm volatile("cp.async.cg.shared.global [%0], [%1], 16;\n"
                 :: "r"(dst_smem), "l"(src_gmem));
}

__device__ __forceinline__ void prefetch_tile(uint32_t sb, const float* __restrict__ in,
                                              int tile, int tid)
{
    const float4* src = (const float4*)(in + (size_t)tile * TILE_FLOATS);
#pragma unroll
    for (int i = 0; i < VEC_FULL; i++)
        cp16(sb + (uint32_t)(tid + i * THREADS) * 16, src + tid + i * THREADS);
    if (tid < VEC_REM)
        cp16(sb + (uint32_t)(tid + VEC_FULL * THREADS) * 16,
             src + tid + VEC_FULL * THREADS);
}

__global__ __launch_bounds__(THREADS) void yolo_post_kernel(
    const float* __restrict__ in, float* __restrict__ out, int ntiles)
{
    __shared__ __align__(16) float buf[STAGES][TILE_FLOATS];

    const int tid  = threadIdx.x;
    const int step = gridDim.x;

    uint32_t sbase[STAGES];
#pragma unroll
    for (int s = 0; s < STAGES; s++)
        sbase[s] = (uint32_t)__cvta_generic_to_shared(buf[s]);

    // Prologue: prefetch tiles j=0,1,2 into stages 0,1,2 (3 committed groups)
#pragma unroll
    for (int p = 0; p < 3; p++) {
        const int t = blockIdx.x + p * step;
        if (t < ntiles)
            prefetch_tile(sbase[p], in, t, tid);
        asm volatile("cp.async.commit_group;\n");
    }

    const int r = tid >> 3;                          // row within tile (0..15)
    const int q = tid & 7;                           // eighth: classes [10q,10q+10)

    int j = 0;
    int tile = blockIdx.x;
    while (tile < ntiles) {
        // Oldest of the <=3 outstanding groups is tile j's data
        asm volatile("cp.async.wait_group 2;\n");
        __syncthreads();   // also: everyone finished computing tile j-1 last iter

        // Prefetch tile j+3 into stage (j+3)%4 (= stage of tile j-1, now free)
        const int pf = tile + 3 * step;
        if (pf < ntiles)
            prefetch_tile(sbase[(j + 3) & 3], in, pf, tid);
        asm volatile("cp.async.commit_group;\n");

        // ---- Compute tile j: 8 lanes per row, 10 classes each ----
        const float* rp = buf[j & 3] + r * ROW_LEN;
        const float* cp = rp + 5 + 10 * q;

        // Two interleaved chains (even/odd c) of depth 5
        float b0 = cp[0]; int i0 = 0;
        float b1 = cp[1]; int i1 = 1;
#pragma unroll
        for (int c = 2; c < 10; c += 2) {
            const float v0 = cp[c];
            const float v1 = cp[c + 1];
            if (v0 > b0) { b0 = v0; i0 = c; }        // strict > : first max
            if (v1 > b1) { b1 = v1; i1 = c + 1; }
        }
        // Merge chains; tie -> smaller index (jnp.argmax first-occurrence)
        float best; int bidx;
        if (b1 > b0 || (b1 == b0 && i1 < i0)) { best = b1; bidx = i1; }
        else                                   { best = b0; bidx = i0; }
        bidx += 10 * q;

        // Combine across the 8-lane group; tie -> lowest class index
#pragma unroll
        for (int off = 1; off <= 4; off <<= 1) {
            const float ob = __shfl_xor_sync(0xffffffffu, best, off);
            const int   oi = __shfl_xor_sync(0xffffffffu, bidx, off);
            if (ob > best || (ob == best && oi < bidx)) { best = ob; bidx = oi; }
        }

        const float conf  = rp[4];
        const float score = conf * best;
        const bool  keep  = score > CONF_THRESH;

        float2* orow = reinterpret_cast<float2*>(out + (size_t)(tile * WROWS + r) * OUT_LEN);
        if (q == 0) {
            const float x = rp[0], y = rp[1], w = rp[2], h = rp[3];
            const float hw = 0.5f * w;
            const float hh = 0.5f * h;
            orow[0] = keep ? make_float2(x - hw, y - hh) : make_float2(0.f, 0.f);
            orow[1] = keep ? make_float2(x + hw, y + hh) : make_float2(0.f, 0.f);
        } else if (q == 1) {
            orow[2] = keep ? make_float2(score, (float)bidx) : make_float2(0.f, 0.f);
        }

        j++;
        tile += step;
    }
}

extern "C" void kernel_launch(void* const* d_in, const int* in_sizes, int n_in,
                              void* d_out, int out_size)
{
    const float* in  = (const float*)d_in[0];
    float*       out = (float*)d_out;

    const int nrows  = in_sizes[0] / ROW_LEN;    // 403200
    const int ntiles = nrows / WROWS;            // 25200 (exact)

    // Persistent grid: 10 blocks/SM x 148 SMs
    const int blocks = 1480;

    yolo_post_kernel<<<blocks, THREADS>>>(in, out, ntiles);
}